// round 1
// baseline (speedup 1.0000x reference)
#include <cuda_runtime.h>

#define N_NODES 50000
#define N_EDGES 800000
#define HDIM    64
#define NCLS    6
#define NGRAPH  500
#define BN_EPS  1e-5f

// ---------------- scratch (allocation-free: __device__ globals) -------------
__device__ __align__(16) float d_t[N_NODES * HDIM];     // post-GEMM features
__device__ __align__(16) float d_agg[N_NODES * HDIM];   // aggregated features
__device__ __align__(16) float d_h[N_NODES * HDIM];     // layer output
__device__ float d_deg[N_NODES];
__device__ float d_dinv[N_NODES];
__device__ float d_norm[N_EDGES];
__device__ float d_sum[HDIM];
__device__ float d_sq[HDIM];
__device__ float d_a[HDIM];   // BN scale
__device__ float d_c[HDIM];   // BN shift (bias folded in)
__device__ __align__(16) float d_pool[NGRAPH * HDIM];
__device__ float d_cnt[NGRAPH];

// ---------------- degree / norm precompute ----------------------------------
__global__ void k_deg_init() {
    int i = blockIdx.x * blockDim.x + threadIdx.x;
    if (i < N_NODES) d_deg[i] = 1.0f;  // self-loop
}

__global__ void k_deg_acc(const int* __restrict__ dst) {
    int e = blockIdx.x * blockDim.x + threadIdx.x;
    if (e < N_EDGES) atomicAdd(&d_deg[dst[e]], 1.0f);
}

__global__ void k_dinv() {
    int i = blockIdx.x * blockDim.x + threadIdx.x;
    if (i < N_NODES) d_dinv[i] = rsqrtf(d_deg[i]);
}

__global__ void k_norm(const int* __restrict__ src, const int* __restrict__ dst) {
    int e = blockIdx.x * blockDim.x + threadIdx.x;
    if (e < N_EDGES) d_norm[e] = d_dinv[src[e]] * d_dinv[dst[e]];
}

// ---------------- dense GEMM: Y[N,64] = X[N,64] @ W[64,64] ------------------
// 512 threads = 8 rows x 64 cols, W staged in shared, K=64 fully unrolled.
__global__ __launch_bounds__(512) void k_gemm(const float* __restrict__ Xext,
                                              const float* __restrict__ W,
                                              int use_ext) {
    __shared__ float Ws[64 * 64];
    __shared__ float Xs[8][64];
    const float* X = use_ext ? Xext : d_h;
    int tid = threadIdx.x;

#pragma unroll
    for (int i = 0; i < 8; i++) Ws[tid + i * 512] = W[tid + i * 512];

    // block 0 also zeroes the BN stat accumulators for this layer
    if (blockIdx.x == 0 && tid < 64) { d_sum[tid] = 0.0f; d_sq[tid] = 0.0f; }

    int r = tid >> 6, col = tid & 63;
    int row = blockIdx.x * 8 + r;               // N divisible by 8
    Xs[r][col] = X[row * 64 + col];
    __syncthreads();

    float acc = 0.0f;
#pragma unroll
    for (int k = 0; k < 64; k++) acc = fmaf(Xs[r][k], Ws[k * 64 + col], acc);
    d_t[row * 64 + col] = acc;
}

// ---------------- aggregation ------------------------------------------------
// agg[i] = dinv[i]^2 * t[i]   (self-loop; also serves as the zero-init)
__global__ void k_selfloop() {
    int i = blockIdx.x * blockDim.x + threadIdx.x;   // N*16 float4 chunks
    if (i >= N_NODES * 16) return;
    int node = i >> 4;
    float s = d_dinv[node];
    s *= s;
    float4 v = ((const float4*)d_t)[i];
    v.x *= s; v.y *= s; v.z *= s; v.w *= s;
    ((float4*)d_agg)[i] = v;
}

// agg[dst] += norm[e] * t[src]  via red.global.add.v4.f32
__global__ void k_edge(const int* __restrict__ src, const int* __restrict__ dst) {
    int i = blockIdx.x * blockDim.x + threadIdx.x;   // E*16 float4 chunks
    if (i >= N_EDGES * 16) return;
    int e = i >> 4, c = i & 15;
    int s = __ldg(src + e);
    int d = __ldg(dst + e);
    float w = __ldg(d_norm + e);
    float4 v = ((const float4*)d_t)[s * 16 + c];
    v.x *= w; v.y *= w; v.z *= w; v.w *= w;
    float* p = d_agg + (d * 64 + c * 4);
    asm volatile("red.global.add.v4.f32 [%0], {%1,%2,%3,%4};"
                 :: "l"(p), "f"(v.x), "f"(v.y), "f"(v.z), "f"(v.w)
                 : "memory");
}

// ---------------- BatchNorm statistics ---------------------------------------
__global__ __launch_bounds__(256) void k_stats(const float* __restrict__ b) {
    int tid = threadIdx.x;
    int col = tid & 63;
    float bb = __ldg(b + col);
    float s = 0.0f, s2 = 0.0f;
    for (int row = blockIdx.x * 4 + (tid >> 6); row < N_NODES; row += gridDim.x * 4) {
        float v = d_agg[row * 64 + col] + bb;
        s += v; s2 += v * v;
    }
    __shared__ float sh[256], sh2[256];
    sh[tid] = s; sh2[tid] = s2;
    __syncthreads();
    if (tid < 64) {
        s  = sh[tid]  + sh[tid + 64]  + sh[tid + 128]  + sh[tid + 192];
        s2 = sh2[tid] + sh2[tid + 64] + sh2[tid + 128] + sh2[tid + 192];
        atomicAdd(&d_sum[col], s);
        atomicAdd(&d_sq[col], s2);
    }
}

// fold mean/var/gamma/beta/bias into per-channel affine (a, c)
__global__ void k_finalize(const float* __restrict__ g,
                           const float* __restrict__ be,
                           const float* __restrict__ b) {
    int c = threadIdx.x;  // 64 threads
    float mu  = d_sum[c] * (1.0f / N_NODES);
    float var = d_sq[c] * (1.0f / N_NODES) - mu * mu;
    float inv = rsqrtf(var + BN_EPS);
    float a = __ldg(g + c) * inv;
    d_a[c] = a;
    d_c[c] = __ldg(be + c) + a * (__ldg(b + c) - mu);
}

// h = relu(agg*a + c)
__global__ void k_bnrelu() {
    int i = blockIdx.x * blockDim.x + threadIdx.x;   // N*16 chunks
    if (i >= N_NODES * 16) return;
    int c4 = (i & 15) * 4;
    float4 v = ((const float4*)d_agg)[i];
    v.x = fmaxf(0.0f, fmaf(v.x, d_a[c4 + 0], d_c[c4 + 0]));
    v.y = fmaxf(0.0f, fmaf(v.y, d_a[c4 + 1], d_c[c4 + 1]));
    v.z = fmaxf(0.0f, fmaf(v.z, d_a[c4 + 2], d_c[c4 + 2]));
    v.w = fmaxf(0.0f, fmaf(v.w, d_a[c4 + 3], d_c[c4 + 3]));
    ((float4*)d_h)[i] = v;
}

// ---------------- pooling + classifier ---------------------------------------
__global__ void k_pool_zero() {
    int i = blockIdx.x * blockDim.x + threadIdx.x;
    if (i < NGRAPH * HDIM) d_pool[i] = 0.0f;
    if (i < NGRAPH) d_cnt[i] = 0.0f;
}

__global__ void k_pool(const int* __restrict__ batch) {
    int i = blockIdx.x * blockDim.x + threadIdx.x;   // N*16 chunks
    if (i >= N_NODES * 16) return;
    int node = i >> 4, c = i & 15;
    int g = __ldg(batch + node);
    float4 v = ((const float4*)d_h)[i];
    float* p = d_pool + (g * 64 + c * 4);
    asm volatile("red.global.add.v4.f32 [%0], {%1,%2,%3,%4};"
                 :: "l"(p), "f"(v.x), "f"(v.y), "f"(v.z), "f"(v.w)
                 : "memory");
    if (c == 0) atomicAdd(&d_cnt[g], 1.0f);
}

__global__ __launch_bounds__(64) void k_fc(const float* __restrict__ fcW,
                                           const float* __restrict__ fcb,
                                           float* __restrict__ out) {
    int g = blockIdx.x;
    int tid = threadIdx.x;  // 64
    __shared__ float p[64];
    float cnt = fmaxf(d_cnt[g], 1.0f);
    p[tid] = d_pool[g * 64 + tid] / cnt;
    __syncthreads();
    if (tid < NCLS) {
        float acc = __ldg(fcb + tid);
#pragma unroll
        for (int k = 0; k < 64; k++)
            acc = fmaf(p[k], __ldg(fcW + k * NCLS + tid), acc);
        out[g * NCLS + tid] = acc;
    }
}

// ---------------- launch ------------------------------------------------------
extern "C" void kernel_launch(void* const* d_in, const int* in_sizes, int n_in,
                              void* d_out, int out_size) {
    const float* x     = (const float*)d_in[0];
    const int*   ei    = (const int*)d_in[1];
    const int*   src   = ei;              // edge_index[0]
    const int*   dst   = ei + N_EDGES;    // edge_index[1]
    const int*   batch = (const int*)d_in[2];
    const float* W[3]  = { (const float*)d_in[3],  (const float*)d_in[7],  (const float*)d_in[11] };
    const float* b[3]  = { (const float*)d_in[4],  (const float*)d_in[8],  (const float*)d_in[12] };
    const float* g[3]  = { (const float*)d_in[5],  (const float*)d_in[9],  (const float*)d_in[13] };
    const float* be[3] = { (const float*)d_in[6],  (const float*)d_in[10], (const float*)d_in[14] };
    const float* fcW   = (const float*)d_in[15];
    const float* fcb   = (const float*)d_in[16];
    float* out = (float*)d_out;

    k_deg_init<<<(N_NODES + 255) / 256, 256>>>();
    k_deg_acc<<<(N_EDGES + 255) / 256, 256>>>(dst);
    k_dinv<<<(N_NODES + 255) / 256, 256>>>();
    k_norm<<<(N_EDGES + 255) / 256, 256>>>(src, dst);

    for (int l = 0; l < 3; l++) {
        k_gemm<<<N_NODES / 8, 512>>>(x, W[l], l == 0 ? 1 : 0);
        k_selfloop<<<(N_NODES * 16 + 255) / 256, 256>>>();
        k_edge<<<(N_EDGES * 16 + 255) / 256, 256>>>(src, dst);
        k_stats<<<512, 256>>>(b[l]);
        k_finalize<<<1, 64>>>(g[l], be[l], b[l]);
        k_bnrelu<<<(N_NODES * 16 + 255) / 256, 256>>>();
    }

    k_pool_zero<<<(NGRAPH * HDIM + 255) / 256, 256>>>();
    k_pool<<<(N_NODES * 16 + 255) / 256, 256>>>(batch);
    k_fc<<<NGRAPH, 64>>>(fcW, fcb, out);
}

// round 3
// speedup vs baseline: 1.5643x; 1.5643x over previous
#include <cuda_runtime.h>

#define N_NODES 50000
#define N_EDGES 800000
#define HDIM    64
#define NCLS    6
#define NGRAPH  500
#define BN_EPS  1e-5f

// ---------------- scratch (allocation-free: __device__ globals) -------------
__device__ __align__(16) float d_t[N_NODES * HDIM];     // post-GEMM features
__device__ __align__(16) float d_agg[N_NODES * HDIM];   // aggregated features
__device__ float d_deg[N_NODES];
__device__ float d_norm[N_EDGES];
__device__ float d_sum[HDIM];
__device__ float d_sq[HDIM];
__device__ __align__(16) float d_a[HDIM];   // BN scale
__device__ __align__(16) float d_c[HDIM];   // BN shift (bias folded in)
__device__ __align__(16) float d_pool[NGRAPH * HDIM];
__device__ float d_cnt[NGRAPH];

// ---------------- degree / norm precompute ----------------------------------
__global__ void k_deg_init() {
    int i = blockIdx.x * blockDim.x + threadIdx.x;
    if (i < N_NODES) d_deg[i] = 1.0f;  // self-loop
}

__global__ void k_deg_acc(const int* __restrict__ dst) {
    int e = blockIdx.x * blockDim.x + threadIdx.x;
    if (e < N_EDGES) atomicAdd(&d_deg[dst[e]], 1.0f);
}

__global__ void k_norm(const int* __restrict__ src, const int* __restrict__ dst) {
    int e = blockIdx.x * blockDim.x + threadIdx.x;
    if (e < N_EDGES)
        d_norm[e] = rsqrtf(d_deg[src[e]]) * rsqrtf(d_deg[dst[e]]);
}

// ---------------- fused GEMM ---------------------------------------------------
// Y[N,64] = act(X)[N,64] @ W[64,64], act = identity (layer 0) or BN-affine+ReLU.
// X is selected IN DEVICE CODE: external input (layer 0) or d_agg (layers 1,2).
// Epilogue writes d_t = Y and d_agg = Y / deg (self-loop init).
// 256 threads, 64-row tile, 4x4 register micro-tile per thread.
__global__ __launch_bounds__(256) void k_gemm(const float* __restrict__ Xext,
                                              const float* __restrict__ W,
                                              int apply_bn) {
    __shared__ float Xs[64][68];   // padded: avoids bank conflicts
    __shared__ float Ws[64][68];

    const float* X = apply_bn ? (const float*)d_agg : Xext;

    int tid = threadIdx.x;
    int tx = tid & 15;             // col group (4 cols)
    int ty = tid >> 4;             // row group (4 rows)
    int base = blockIdx.x * 64;

    if (blockIdx.x == 0 && tid < 64) { d_sum[tid] = 0.0f; d_sq[tid] = 0.0f; }

    // stage W[k][c]: 4 iterations, each thread one float4
    {
        int k = tid >> 4;          // 0..15 (+16 per iter)
        int cg = tid & 15;
#pragma unroll
        for (int i = 0; i < 4; i++) {
            float4 w = ((const float4*)W)[(k + i * 16) * 16 + cg];
            *(float4*)&Ws[k + i * 16][cg * 4] = w;
        }
    }

    // stage X tile with optional fused BN-affine + ReLU
    {
        int rl = tid >> 4;         // local row 0..15 (+16 per iter)
        int cg = tid & 15;
        float4 a4 = make_float4(0.f, 0.f, 0.f, 0.f);
        float4 c4 = make_float4(0.f, 0.f, 0.f, 0.f);
        if (apply_bn) {
            a4 = ((const float4*)d_a)[cg];
            c4 = ((const float4*)d_c)[cg];
        }
#pragma unroll
        for (int i = 0; i < 4; i++) {
            int row = base + rl + i * 16;
            float4 v = make_float4(0.f, 0.f, 0.f, 0.f);
            if (row < N_NODES) v = ((const float4*)X)[row * 16 + cg];
            if (apply_bn) {
                v.x = fmaxf(0.0f, fmaf(v.x, a4.x, c4.x));
                v.y = fmaxf(0.0f, fmaf(v.y, a4.y, c4.y));
                v.z = fmaxf(0.0f, fmaf(v.z, a4.z, c4.z));
                v.w = fmaxf(0.0f, fmaf(v.w, a4.w, c4.w));
            }
            *(float4*)&Xs[rl + i * 16][cg * 4] = v;
        }
    }
    __syncthreads();

    float acc[4][4];
#pragma unroll
    for (int i = 0; i < 4; i++)
#pragma unroll
        for (int j = 0; j < 4; j++) acc[i][j] = 0.0f;

#pragma unroll 8
    for (int k = 0; k < 64; k++) {
        float4 w = *(const float4*)&Ws[k][tx * 4];
        float x0 = Xs[ty * 4 + 0][k];
        float x1 = Xs[ty * 4 + 1][k];
        float x2 = Xs[ty * 4 + 2][k];
        float x3 = Xs[ty * 4 + 3][k];
        acc[0][0] = fmaf(x0, w.x, acc[0][0]); acc[0][1] = fmaf(x0, w.y, acc[0][1]);
        acc[0][2] = fmaf(x0, w.z, acc[0][2]); acc[0][3] = fmaf(x0, w.w, acc[0][3]);
        acc[1][0] = fmaf(x1, w.x, acc[1][0]); acc[1][1] = fmaf(x1, w.y, acc[1][1]);
        acc[1][2] = fmaf(x1, w.z, acc[1][2]); acc[1][3] = fmaf(x1, w.w, acc[1][3]);
        acc[2][0] = fmaf(x2, w.x, acc[2][0]); acc[2][1] = fmaf(x2, w.y, acc[2][1]);
        acc[2][2] = fmaf(x2, w.z, acc[2][2]); acc[2][3] = fmaf(x2, w.w, acc[2][3]);
        acc[3][0] = fmaf(x3, w.x, acc[3][0]); acc[3][1] = fmaf(x3, w.y, acc[3][1]);
        acc[3][2] = fmaf(x3, w.z, acc[3][2]); acc[3][3] = fmaf(x3, w.w, acc[3][3]);
    }

    // epilogue: d_t = Y, d_agg = Y / deg (fused self-loop)
#pragma unroll
    for (int i = 0; i < 4; i++) {
        int row = base + ty * 4 + i;
        if (row < N_NODES) {
            float s = 1.0f / d_deg[row];
            float4 t = make_float4(acc[i][0], acc[i][1], acc[i][2], acc[i][3]);
            float4 g = make_float4(t.x * s, t.y * s, t.z * s, t.w * s);
            ((float4*)d_t)[row * 16 + tx] = t;
            ((float4*)d_agg)[row * 16 + tx] = g;
        }
    }
}

// ---------------- edge scatter: agg[dst] += norm[e] * t[src] ------------------
__global__ void k_edge(const int* __restrict__ src, const int* __restrict__ dst) {
    int i = blockIdx.x * blockDim.x + threadIdx.x;   // E*16 float4 chunks
    if (i >= N_EDGES * 16) return;
    int e = i >> 4, c = i & 15;
    int s = __ldg(src + e);
    int d = __ldg(dst + e);
    float w = __ldg(d_norm + e);
    float4 v = ((const float4*)d_t)[s * 16 + c];
    v.x *= w; v.y *= w; v.z *= w; v.w *= w;
    float* p = d_agg + (d * 64 + c * 4);
    asm volatile("red.global.add.v4.f32 [%0], {%1,%2,%3,%4};"
                 :: "l"(p), "f"(v.x), "f"(v.y), "f"(v.z), "f"(v.w)
                 : "memory");
}

// ---------------- BatchNorm statistics (vectorized) ---------------------------
__global__ __launch_bounds__(256) void k_stats(const float* __restrict__ b) {
    int tid = threadIdx.x;
    int cg = tid & 15;
    float4 bb = ((const float4*)b)[cg];
    float4 s = make_float4(0.f, 0.f, 0.f, 0.f);
    float4 s2 = make_float4(0.f, 0.f, 0.f, 0.f);
    for (int row = blockIdx.x * 16 + (tid >> 4); row < N_NODES; row += gridDim.x * 16) {
        float4 v = ((const float4*)d_agg)[row * 16 + cg];
        v.x += bb.x; v.y += bb.y; v.z += bb.z; v.w += bb.w;
        s.x += v.x; s.y += v.y; s.z += v.z; s.w += v.w;
        s2.x += v.x * v.x; s2.y += v.y * v.y; s2.z += v.z * v.z; s2.w += v.w * v.w;
    }
    __shared__ float sh[256 * 4], sh2[256 * 4];
    *(float4*)&sh[tid * 4] = s;
    *(float4*)&sh2[tid * 4] = s2;
    __syncthreads();
    if (tid < 64) {                       // tid = column; cgc = tid>>2, j = tid&3
        int cgc = tid >> 2, j = tid & 3;
        float a = 0.f, a2 = 0.f;
#pragma unroll
        for (int rt = 0; rt < 16; rt++) {
            a  += sh[(rt * 16 + cgc) * 4 + j];
            a2 += sh2[(rt * 16 + cgc) * 4 + j];
        }
        atomicAdd(&d_sum[tid], a);
        atomicAdd(&d_sq[tid], a2);
    }
}

// fold mean/var/gamma/beta/bias into per-channel affine (a, c)
__global__ void k_finalize(const float* __restrict__ g,
                           const float* __restrict__ be,
                           const float* __restrict__ b) {
    int c = threadIdx.x;  // 64 threads
    float mu  = d_sum[c] * (1.0f / N_NODES);
    float var = d_sq[c] * (1.0f / N_NODES) - mu * mu;
    float inv = rsqrtf(var + BN_EPS);
    float a = __ldg(g + c) * inv;
    d_a[c] = a;
    d_c[c] = __ldg(be + c) + a * (__ldg(b + c) - mu);
}

// ---------------- pooling (fused BN+ReLU of layer 3) + classifier -------------
__global__ void k_pool_zero() {
    int i = blockIdx.x * blockDim.x + threadIdx.x;
    if (i < NGRAPH * HDIM) d_pool[i] = 0.0f;
    if (i < NGRAPH) d_cnt[i] = 0.0f;
}

__global__ void k_pool(const int* __restrict__ batch) {
    int i = blockIdx.x * blockDim.x + threadIdx.x;   // N*16 chunks
    if (i >= N_NODES * 16) return;
    int node = i >> 4, c = i & 15;
    int g = __ldg(batch + node);
    float4 a4 = ((const float4*)d_a)[c];
    float4 c4 = ((const float4*)d_c)[c];
    float4 v = ((const float4*)d_agg)[i];
    v.x = fmaxf(0.0f, fmaf(v.x, a4.x, c4.x));
    v.y = fmaxf(0.0f, fmaf(v.y, a4.y, c4.y));
    v.z = fmaxf(0.0f, fmaf(v.z, a4.z, c4.z));
    v.w = fmaxf(0.0f, fmaf(v.w, a4.w, c4.w));
    float* p = d_pool + (g * 64 + c * 4);
    asm volatile("red.global.add.v4.f32 [%0], {%1,%2,%3,%4};"
                 :: "l"(p), "f"(v.x), "f"(v.y), "f"(v.z), "f"(v.w)
                 : "memory");
    if (c == 0) atomicAdd(&d_cnt[g], 1.0f);
}

__global__ __launch_bounds__(64) void k_fc(const float* __restrict__ fcW,
                                           const float* __restrict__ fcb,
                                           float* __restrict__ out) {
    int g = blockIdx.x;
    int tid = threadIdx.x;  // 64
    __shared__ float p[64];
    float cnt = fmaxf(d_cnt[g], 1.0f);
    p[tid] = d_pool[g * 64 + tid] / cnt;
    __syncthreads();
    if (tid < NCLS) {
        float acc = __ldg(fcb + tid);
#pragma unroll
        for (int k = 0; k < 64; k++)
            acc = fmaf(p[k], __ldg(fcW + k * NCLS + tid), acc);
        out[g * NCLS + tid] = acc;
    }
}

// ---------------- launch ------------------------------------------------------
extern "C" void kernel_launch(void* const* d_in, const int* in_sizes, int n_in,
                              void* d_out, int out_size) {
    const float* x     = (const float*)d_in[0];
    const int*   ei    = (const int*)d_in[1];
    const int*   src   = ei;              // edge_index[0]
    const int*   dst   = ei + N_EDGES;    // edge_index[1]
    const int*   batch = (const int*)d_in[2];
    const float* W[3]  = { (const float*)d_in[3],  (const float*)d_in[7],  (const float*)d_in[11] };
    const float* b[3]  = { (const float*)d_in[4],  (const float*)d_in[8],  (const float*)d_in[12] };
    const float* g[3]  = { (const float*)d_in[5],  (const float*)d_in[9],  (const float*)d_in[13] };
    const float* be[3] = { (const float*)d_in[6],  (const float*)d_in[10], (const float*)d_in[14] };
    const float* fcW   = (const float*)d_in[15];
    const float* fcb   = (const float*)d_in[16];
    float* out = (float*)d_out;

    k_deg_init<<<(N_NODES + 255) / 256, 256>>>();
    k_deg_acc<<<(N_EDGES + 255) / 256, 256>>>(dst);
    k_norm<<<(N_EDGES + 255) / 256, 256>>>(src, dst);

    const int gemm_grid = (N_NODES + 63) / 64;
    for (int l = 0; l < 3; l++) {
        // apply_bn selects d_agg as input inside the kernel (device-side pointer)
        k_gemm<<<gemm_grid, 256>>>(x, W[l], l == 0 ? 0 : 1);
        k_edge<<<(N_EDGES * 16 + 255) / 256, 256>>>(src, dst);
        k_stats<<<256, 256>>>(b[l]);
        k_finalize<<<1, 64>>>(g[l], be[l], b[l]);
    }

    k_pool_zero<<<(NGRAPH * HDIM + 255) / 256, 256>>>();
    k_pool<<<(N_NODES * 16 + 255) / 256, 256>>>(batch);
    k_fc<<<NGRAPH, 64>>>(fcW, fcb, out);
}